// round 6
// baseline (speedup 1.0000x reference)
#include <cuda_runtime.h>
#include <math_constants.h>

// Problem constants (fixed instance: B=4, L=4096, H=8, D=64, sample_k=n_top=45)
#define Bq  4
#define Lq  4096
#define Hq  8
#define Dq  64
#define Sq  45      // sample_k
#define Uq  45      // n_top
#define BHq 32
#define NKC 8       // key chunks for split-K attn*V
#define KCS 512     // keys per chunk

// ---------------- scratch (device globals: alloc-free) ----------------
__device__ float g_M[BHq * Lq];                 // 512 KB
__device__ int   g_top[BHq * Uq];
__device__ float g_scores[BHq * Uq * Lq];       // 23.6 MB
__device__ float g_rowmax[BHq * Uq];
__device__ float g_rowsum[BHq * Uq];
__device__ float g_part[BHq * NKC * Uq * Dq];   // 2.95 MB split-K partials
__device__ float g_meanp[BHq * 16 * Dq];        // V-mean partials
__device__ float g_meanv[BHq * Dq];

// ---------------- Stage 1: M[b,h,l] = max_s(q.k_s) - sum_s(q.k_s)/L ----------------
// One warp per (bh, l). Lane-per-sample: each lane computes one full 64-d dot
// (fp32, float4 gathers), then a single 5-step butterfly for max and sum.
__global__ void __launch_bounds__(256) kernel_m(const float* __restrict__ Q,
                                                const float* __restrict__ K,
                                                const int*   __restrict__ idx) {
    int wg   = blockIdx.x * 8 + (threadIdx.x >> 5);
    int lane = threadIdx.x & 31;
    int l  = wg & (Lq - 1);
    int bh = wg >> 12;
    int b = bh >> 3, h = bh & 7;

    const float4* qrow = (const float4*)(Q + (((size_t)b * Lq + l) * Hq + h) * Dq);
    float4 q[16];
#pragma unroll
    for (int i = 0; i < 16; i++) q[i] = qrow[i];

    float lm = -CUDART_INF_F;
    float ls = 0.f;
#pragma unroll
    for (int r = 0; r < 2; r++) {
        int s = lane + 32 * r;
        if (s < Sq) {
            int j = idx[l * Sq + s];
            const float4* krow = (const float4*)(K + (((size_t)b * Lq + j) * Hq + h) * Dq);
            float dot = 0.f;
#pragma unroll
            for (int i = 0; i < 16; i++) {
                float4 kv = krow[i];
                dot = fmaf(q[i].x, kv.x, dot);
                dot = fmaf(q[i].y, kv.y, dot);
                dot = fmaf(q[i].z, kv.z, dot);
                dot = fmaf(q[i].w, kv.w, dot);
            }
            lm = fmaxf(lm, dot);
            ls += dot;
        }
    }
#pragma unroll
    for (int o = 16; o > 0; o >>= 1) {
        lm = fmaxf(lm, __shfl_xor_sync(0xffffffffu, lm, o));
        ls += __shfl_xor_sync(0xffffffffu, ls, o);
    }
    if (lane == 0) g_M[bh * Lq + l] = lm - ls * (1.f / Lq);
}

// ---------------- Stage 2: top-45 per (b,h), stable (lowest index on ties) ----------------
__global__ void __launch_bounds__(256) kernel_topk() {
    int bh = blockIdx.x;
    __shared__ float v[Lq];
    __shared__ float bv[256];
    __shared__ int   bi[256];
    int t = threadIdx.x;
    for (int i = t; i < Lq; i += 256) v[i] = g_M[bh * Lq + i];
    __syncthreads();
    for (int u = 0; u < Uq; u++) {
        float best = -CUDART_INF_F;
        int   besti = Lq;
        for (int i = t; i < Lq; i += 256) {
            float x = v[i];
            if (x > best) { best = x; besti = i; }   // strided ascending -> lowest idx kept on tie
        }
        bv[t] = best; bi[t] = besti;
        __syncthreads();
        for (int st = 128; st > 0; st >>= 1) {
            if (t < st) {
                if (bv[t + st] > bv[t] || (bv[t + st] == bv[t] && bi[t + st] < bi[t])) {
                    bv[t] = bv[t + st]; bi[t] = bi[t + st];
                }
            }
            __syncthreads();
        }
        if (t == 0) { g_top[bh * Uq + u] = bi[0]; v[bi[0]] = -CUDART_INF_F; }
        __syncthreads();
    }
}

// ---------------- Stage 3a: scores[bh][u][k] = (Qr[u] . K[k]) / 8 ----------------
// CTA per (bh, 128-key block). Register-tiled 3x8 per thread, padded smem (stride 65).
__global__ void __launch_bounds__(256) kernel_scores(const float* __restrict__ Q,
                                                     const float* __restrict__ K) {
    __shared__ float Qs[Uq * 65];
    __shared__ float Ks[128 * 65];
    int bh = blockIdx.y;
    int kb = blockIdx.x;
    int b = bh >> 3, h = bh & 7;
    int tid = threadIdx.x;

    for (int e = tid; e < Uq * Dq; e += 256) {
        int u = e >> 6, d = e & 63;
        int row = g_top[bh * Uq + u];
        Qs[u * 65 + d] = Q[(((size_t)b * Lq + row) * Hq + h) * Dq + d];
    }
    int k0 = kb * 128;
    for (int e = tid; e < 128 * Dq; e += 256) {
        int k = e >> 6, d = e & 63;
        Ks[k * 65 + d] = K[(((size_t)b * Lq + k0 + k) * Hq + h) * Dq + d];
    }
    __syncthreads();

    int tu = tid >> 4, tk = tid & 15;
    float acc[3][8];
#pragma unroll
    for (int r = 0; r < 3; r++)
#pragma unroll
        for (int j = 0; j < 8; j++) acc[r][j] = 0.f;

#pragma unroll 4
    for (int d = 0; d < Dq; d++) {
        float qv[3];
#pragma unroll
        for (int r = 0; r < 3; r++) {
            int u = tu + 16 * r;
            qv[r] = (u < Uq) ? Qs[u * 65 + d] : 0.f;
        }
        float kv[8];
#pragma unroll
        for (int j = 0; j < 8; j++) kv[j] = Ks[(tk + 16 * j) * 65 + d];
#pragma unroll
        for (int r = 0; r < 3; r++)
#pragma unroll
            for (int j = 0; j < 8; j++) acc[r][j] = fmaf(qv[r], kv[j], acc[r][j]);
    }
#pragma unroll
    for (int r = 0; r < 3; r++) {
        int u = tu + 16 * r;
        if (u < Uq) {
#pragma unroll
            for (int j = 0; j < 8; j++)
                g_scores[(bh * Uq + u) * Lq + k0 + tk + 16 * j] = acc[r][j] * 0.125f;
        }
    }
}

// ---------------- Stage 3b: per-row max and sum(exp) ----------------
__global__ void __launch_bounds__(256) kernel_rowstats() {
    int bh = blockIdx.x / Uq, u = blockIdx.x % Uq;
    const float* row = g_scores + (bh * Uq + u) * Lq;
    __shared__ float red[256];
    int t = threadIdx.x;

    float m = -CUDART_INF_F;
    for (int i = t; i < Lq; i += 256) m = fmaxf(m, row[i]);
    red[t] = m; __syncthreads();
    for (int st = 128; st > 0; st >>= 1) {
        if (t < st) red[t] = fmaxf(red[t], red[t + st]);
        __syncthreads();
    }
    float rm = red[0];
    __syncthreads();

    float s = 0.f;
    for (int i = t; i < Lq; i += 256) s += expf(row[i] - rm);
    red[t] = s; __syncthreads();
    for (int st = 128; st > 0; st >>= 1) {
        if (t < st) red[t] += red[t + st];
        __syncthreads();
    }
    if (t == 0) { g_rowmax[bh * Uq + u] = rm; g_rowsum[bh * Uq + u] = red[0]; }
}

// ---------------- Stage 3c: split-K partial upd[u][d] = sum_k w[u,k] * V[k,d] ----------------
__global__ void __launch_bounds__(256) kernel_updpart(const float* __restrict__ V) {
    __shared__ float Vs[64 * 65];
    __shared__ float Ws[Uq * 65];
    int bh = blockIdx.y;
    int kc = blockIdx.x;   // 0..7
    int b = bh >> 3, h = bh & 7;
    int tid = threadIdx.x;
    int tu = tid >> 4, td = tid & 15;

    float acc[3][4];
#pragma unroll
    for (int r = 0; r < 3; r++)
#pragma unroll
        for (int j = 0; j < 4; j++) acc[r][j] = 0.f;

    for (int sub = 0; sub < 8; sub++) {
        int kbase = kc * KCS + sub * 64;
        for (int e = tid; e < 64 * 64; e += 256) {
            int k = e >> 6, d = e & 63;
            Vs[k * 65 + d] = V[(((size_t)b * Lq + kbase + k) * Hq + h) * Dq + d];
        }
        for (int e = tid; e < Uq * 64; e += 256) {
            int u = e >> 6, k = e & 63;
            Ws[u * 65 + k] = expf(g_scores[(bh * Uq + u) * Lq + kbase + k] - g_rowmax[bh * Uq + u]);
        }
        __syncthreads();
#pragma unroll 4
        for (int k = 0; k < 64; k++) {
            float wv[3];
#pragma unroll
            for (int r = 0; r < 3; r++) {
                int u = tu + 16 * r;
                wv[r] = (u < Uq) ? Ws[u * 65 + k] : 0.f;
            }
            float vv[4];
#pragma unroll
            for (int j = 0; j < 4; j++) vv[j] = Vs[k * 65 + td + 16 * j];
#pragma unroll
            for (int r = 0; r < 3; r++)
#pragma unroll
                for (int j = 0; j < 4; j++) acc[r][j] = fmaf(wv[r], vv[j], acc[r][j]);
        }
        __syncthreads();
    }
#pragma unroll
    for (int r = 0; r < 3; r++) {
        int u = tu + 16 * r;
        if (u < Uq) {
#pragma unroll
            for (int j = 0; j < 4; j++)
                g_part[((bh * NKC + kc) * Uq + u) * Dq + td + 16 * j] = acc[r][j];
        }
    }
}

// ---------------- Stage 4: V mean (partials, then fixed-order combine) ----------------
__global__ void __launch_bounds__(256) kernel_meanpart(const float* __restrict__ V) {
    int lc = blockIdx.x;   // 0..15, 256 l's each
    int bh = blockIdx.y;
    int b = bh >> 3, h = bh & 7;
    int tid = threadIdx.x;
    int d = tid & 63, c = tid >> 6;  // c: 0..3, 64 l's each
    __shared__ float red[256];
    float s = 0.f;
    int lb = lc * 256 + c * 64;
    for (int i = 0; i < 64; i++)
        s += V[(((size_t)b * Lq + lb + i) * Hq + h) * Dq + d];
    red[tid] = s;
    __syncthreads();
    if (c == 0)
        g_meanp[(bh * 16 + lc) * Dq + d] = red[d] + red[64 + d] + red[128 + d] + red[192 + d];
}

__global__ void __launch_bounds__(256) kernel_meancomb() {
    int e = blockIdx.x * 256 + threadIdx.x;
    if (e >= BHq * Dq) return;
    int bh = e >> 6, d = e & 63;
    float s = 0.f;
#pragma unroll
    for (int lc = 0; lc < 16; lc++) s += g_meanp[(bh * 16 + lc) * Dq + d];
    g_meanv[bh * Dq + d] = s * (1.f / Lq);
}

// ---------------- Stage 5: broadcast fill of context with V mean (float4 stores) ----------------
__global__ void __launch_bounds__(256) kernel_fill(float4* __restrict__ out) {
    int i = blockIdx.x * 256 + threadIdx.x;      // 2097152 float4's
    int bh = i >> 16;
    int d4 = i & 15;
    out[i] = ((const float4*)g_meanv)[bh * 16 + d4];
}

// ---------------- Stage 6: reduce split-K partials, normalize, scatter into output ----------------
__global__ void __launch_bounds__(256) kernel_final(float* __restrict__ out) {
    int e = blockIdx.x * 256 + threadIdx.x;
    if (e >= BHq * Uq * Dq) return;
    int d = e & 63;
    int t = e >> 6;
    int u = t % Uq;
    int bh = t / Uq;
    float s = 0.f;
#pragma unroll
    for (int c = 0; c < NKC; c++) s += g_part[((bh * NKC + c) * Uq + u) * Dq + d];
    s /= g_rowsum[bh * Uq + u];
    int row = g_top[bh * Uq + u];
    out[((size_t)bh * Lq + row) * Dq + d] = s;
}

// ---------------- launch ----------------
extern "C" void kernel_launch(void* const* d_in, const int* in_sizes, int n_in,
                              void* d_out, int out_size) {
    const float* Q   = (const float*)d_in[0];
    const float* K   = (const float*)d_in[1];
    const float* V   = (const float*)d_in[2];
    const int*   idx = (const int*)d_in[3];
    float* out = (float*)d_out;

    kernel_m       <<<(BHq * Lq) / 8, 256>>>(Q, K, idx);
    kernel_topk    <<<BHq, 256>>>();
    kernel_scores  <<<dim3(Lq / 128, BHq), 256>>>(Q, K);
    kernel_rowstats<<<BHq * Uq, 256>>>();
    kernel_updpart <<<dim3(NKC, BHq), 256>>>(V);
    kernel_meanpart<<<dim3(16, BHq), 256>>>(V);
    kernel_meancomb<<<(BHq * Dq + 255) / 256, 256>>>();
    kernel_fill    <<<(BHq * Lq * Dq / 4) / 256, 256>>>((float4*)out);
    kernel_final   <<<(BHq * Uq * Dq + 255) / 256, 256>>>(out);
}

// round 7
// speedup vs baseline: 1.2762x; 1.2762x over previous
#include <cuda_runtime.h>
#include <math_constants.h>

// Problem constants (fixed instance: B=4, L=4096, H=8, D=64, sample_k=n_top=45)
#define Bq  4
#define Lq  4096
#define Hq  8
#define Dq  64
#define Sq  45      // sample_k
#define Uq  45      // n_top
#define BHq 32
#define NKC 8       // key chunks for split-K attn*V
#define KCS 512     // keys per chunk
#define NKB 32      // 128-key blocks per row (Lq/128) for partial softmax stats

// ---------------- scratch (device globals: alloc-free) ----------------
__device__ float g_M[BHq * Lq];                 // 512 KB
__device__ int   g_top[BHq * Uq];
__device__ float g_scores[BHq * Uq * Lq];       // 23.6 MB
__device__ float g_pmax[BHq * Uq * NKB];        // per-key-block max
__device__ float g_psum[BHq * Uq * NKB];        // per-key-block sum(exp(.-blockmax))
__device__ float g_rowmax[BHq * Uq];
__device__ float g_rowsum[BHq * Uq];
__device__ float g_part[BHq * NKC * Uq * Dq];   // split-K partials
__device__ float g_meanp[BHq * 16 * Dq];        // V-mean partials
__device__ float g_meanv[BHq * Dq];

// ---------------- Stage 1: M[b,h,l] = max_s(q.k_s) - sum_s(q.k_s)/L ----------------
// CTA = 128 threads = 4 queries (one warp each). All 180 sampled K rows are
// staged into smem with COALESCED 16-thread-per-row float4 loads (2 L1tex
// wavefronts per 256B row instead of 16 for the old per-lane strided walk).
// Rows padded to 17 float4 (68 floats): LDS.128 phase banks = 4*lane mod 32,
// conflict-free. Compute stays lane-per-sample (one 5-step butterfly per query).
__global__ void __launch_bounds__(128) kernel_m(const float* __restrict__ Q,
                                                const float* __restrict__ K,
                                                const int*   __restrict__ idx) {
    __shared__ float4 ks[4 * Sq * 17];           // 48,960 B
    int tid = threadIdx.x;
    int bh = blockIdx.x >> 10;                   // 1024 CTAs per (b,h)
    int l0 = (blockIdx.x & 1023) * 4;
    int b = bh >> 3, h = bh & 7;

    int w    = tid >> 5;
    int lane = tid & 31;
    int l = l0 + w;

    // q row into registers (uniform per warp -> broadcast loads, cheap)
    const float4* qrow = (const float4*)(Q + (((size_t)b * Lq + l) * Hq + h) * Dq);
    float4 q[16];
#pragma unroll
    for (int i = 0; i < 16; i++) q[i] = qrow[i];

    // cooperative coalesced gather of 180 K rows
    for (int e = tid; e < 4 * Sq * 16; e += 128) {
        int row = e >> 4, seg = e & 15;
        int qw = row / Sq, s = row - qw * Sq;
        int j = idx[(l0 + qw) * Sq + s];
        ks[row * 17 + seg] =
            ((const float4*)(K + (((size_t)b * Lq + j) * Hq + h) * Dq))[seg];
    }
    __syncthreads();

    float lm = -CUDART_INF_F;
    float ls = 0.f;
#pragma unroll
    for (int r = 0; r < 2; r++) {
        int s = lane + 32 * r;
        if (s < Sq) {
            const float4* kr = &ks[(w * Sq + s) * 17];
            float dot = 0.f;
#pragma unroll
            for (int i = 0; i < 16; i++) {
                float4 kv = kr[i];
                dot = fmaf(q[i].x, kv.x, dot);
                dot = fmaf(q[i].y, kv.y, dot);
                dot = fmaf(q[i].z, kv.z, dot);
                dot = fmaf(q[i].w, kv.w, dot);
            }
            lm = fmaxf(lm, dot);
            ls += dot;
        }
    }
#pragma unroll
    for (int o = 16; o > 0; o >>= 1) {
        lm = fmaxf(lm, __shfl_xor_sync(0xffffffffu, lm, o));
        ls += __shfl_xor_sync(0xffffffffu, ls, o);
    }
    if (lane == 0) g_M[bh * Lq + l] = lm - ls * (1.f / Lq);
}

// ---------------- Stage 2: top-45 per (b,h), stable (lowest index on ties) ----------------
__global__ void __launch_bounds__(256) kernel_topk() {
    int bh = blockIdx.x;
    __shared__ float v[Lq];
    __shared__ float bv[256];
    __shared__ int   bi[256];
    int t = threadIdx.x;
    for (int i = t; i < Lq; i += 256) v[i] = g_M[bh * Lq + i];
    __syncthreads();
    for (int u = 0; u < Uq; u++) {
        float best = -CUDART_INF_F;
        int   besti = Lq;
        for (int i = t; i < Lq; i += 256) {
            float x = v[i];
            if (x > best) { best = x; besti = i; }   // strided ascending -> lowest idx kept on tie
        }
        bv[t] = best; bi[t] = besti;
        __syncthreads();
        for (int st = 128; st > 0; st >>= 1) {
            if (t < st) {
                if (bv[t + st] > bv[t] || (bv[t + st] == bv[t] && bi[t + st] < bi[t])) {
                    bv[t] = bv[t + st]; bi[t] = bi[t + st];
                }
            }
            __syncthreads();
        }
        if (t == 0) { g_top[bh * Uq + u] = bi[0]; v[bi[0]] = -CUDART_INF_F; }
        __syncthreads();
    }
}

// ---------------- Stage 3a: scores + fused per-block softmax stats ----------------
// CTA per (bh, 128-key block). Register-tiled 3x8 per thread, padded smem.
// After the GEMM-let, each 16-lane tk-group reduces its u-row's block max and
// sum(exp) via intra-half-warp shuffles and writes one partial per block.
__global__ void __launch_bounds__(256) kernel_scores(const float* __restrict__ Q,
                                                     const float* __restrict__ K) {
    __shared__ float Qs[Uq * 65];
    __shared__ float Ks[128 * 65];
    int bh = blockIdx.y;
    int kb = blockIdx.x;
    int b = bh >> 3, h = bh & 7;
    int tid = threadIdx.x;

    for (int e = tid; e < Uq * Dq; e += 256) {
        int u = e >> 6, d = e & 63;
        int row = g_top[bh * Uq + u];
        Qs[u * 65 + d] = Q[(((size_t)b * Lq + row) * Hq + h) * Dq + d];
    }
    int k0 = kb * 128;
    for (int e = tid; e < 128 * Dq; e += 256) {
        int k = e >> 6, d = e & 63;
        Ks[k * 65 + d] = K[(((size_t)b * Lq + k0 + k) * Hq + h) * Dq + d];
    }
    __syncthreads();

    int tu = tid >> 4, tk = tid & 15;
    float acc[3][8];
#pragma unroll
    for (int r = 0; r < 3; r++)
#pragma unroll
        for (int j = 0; j < 8; j++) acc[r][j] = 0.f;

#pragma unroll 4
    for (int d = 0; d < Dq; d++) {
        float qv[3];
#pragma unroll
        for (int r = 0; r < 3; r++) {
            int u = tu + 16 * r;
            qv[r] = (u < Uq) ? Qs[u * 65 + d] : 0.f;
        }
        float kv[8];
#pragma unroll
        for (int j = 0; j < 8; j++) kv[j] = Ks[(tk + 16 * j) * 65 + d];
#pragma unroll
        for (int r = 0; r < 3; r++)
#pragma unroll
            for (int j = 0; j < 8; j++) acc[r][j] = fmaf(qv[r], kv[j], acc[r][j]);
    }

#pragma unroll
    for (int r = 0; r < 3; r++) {
        int u = tu + 16 * r;
        // scaled scores
        float sc[8];
#pragma unroll
        for (int j = 0; j < 8; j++) sc[j] = acc[r][j] * 0.125f;
        if (u < Uq) {
#pragma unroll
            for (int j = 0; j < 8; j++)
                g_scores[(bh * Uq + u) * Lq + k0 + tk + 16 * j] = sc[j];
        }
        // block max over this u-row's 128 keys (16-lane group, offsets<16 stay in half)
        float m = sc[0];
#pragma unroll
        for (int j = 1; j < 8; j++) m = fmaxf(m, sc[j]);
#pragma unroll
        for (int o = 8; o > 0; o >>= 1) m = fmaxf(m, __shfl_xor_sync(0xffffffffu, m, o));
        float s = 0.f;
#pragma unroll
        for (int j = 0; j < 8; j++) s += expf(sc[j] - m);
#pragma unroll
        for (int o = 8; o > 0; o >>= 1) s += __shfl_xor_sync(0xffffffffu, s, o);
        if (tk == 0 && u < Uq) {
            g_pmax[(bh * Uq + u) * NKB + kb] = m;
            g_psum[(bh * Uq + u) * NKB + kb] = s;
        }
    }
}

// ---------------- Stage 3b: combine 32 block partials -> row max / row sum ----------------
__global__ void __launch_bounds__(256) kernel_comb() {
    int gw = blockIdx.x * 8 + (threadIdx.x >> 5);   // one warp per (bh,u) row
    if (gw >= BHq * Uq) return;
    int lane = threadIdx.x & 31;
    float pm = g_pmax[gw * NKB + lane];
    float ps = g_psum[gw * NKB + lane];
    float rm = pm;
#pragma unroll
    for (int o = 16; o > 0; o >>= 1) rm = fmaxf(rm, __shfl_xor_sync(0xffffffffu, rm, o));
    float c = ps * expf(pm - rm);
#pragma unroll
    for (int o = 16; o > 0; o >>= 1) c += __shfl_xor_sync(0xffffffffu, c, o);
    if (lane == 0) { g_rowmax[gw] = rm; g_rowsum[gw] = c; }
}

// ---------------- Stage 3c: split-K partial upd[u][d] = sum_k w[u,k] * V[k,d] ----------------
__global__ void __launch_bounds__(256) kernel_updpart(const float* __restrict__ V) {
    __shared__ float Vs[64 * 65];
    __shared__ float Ws[Uq * 65];
    int bh = blockIdx.y;
    int kc = blockIdx.x;   // 0..7
    int b = bh >> 3, h = bh & 7;
    int tid = threadIdx.x;
    int tu = tid >> 4, td = tid & 15;

    float acc[3][4];
#pragma unroll
    for (int r = 0; r < 3; r++)
#pragma unroll
        for (int j = 0; j < 4; j++) acc[r][j] = 0.f;

    for (int sub = 0; sub < 8; sub++) {
        int kbase = kc * KCS + sub * 64;
        for (int e = tid; e < 64 * 64; e += 256) {
            int k = e >> 6, d = e & 63;
            Vs[k * 65 + d] = V[(((size_t)b * Lq + kbase + k) * Hq + h) * Dq + d];
        }
        for (int e = tid; e < Uq * 64; e += 256) {
            int u = e >> 6, k = e & 63;
            Ws[u * 65 + k] = expf(g_scores[(bh * Uq + u) * Lq + kbase + k] - g_rowmax[bh * Uq + u]);
        }
        __syncthreads();
#pragma unroll 4
        for (int k = 0; k < 64; k++) {
            float wv[3];
#pragma unroll
            for (int r = 0; r < 3; r++) {
                int u = tu + 16 * r;
                wv[r] = (u < Uq) ? Ws[u * 65 + k] : 0.f;
            }
            float vv[4];
#pragma unroll
            for (int j = 0; j < 4; j++) vv[j] = Vs[k * 65 + td + 16 * j];
#pragma unroll
            for (int r = 0; r < 3; r++)
#pragma unroll
                for (int j = 0; j < 4; j++) acc[r][j] = fmaf(wv[r], vv[j], acc[r][j]);
        }
        __syncthreads();
    }
#pragma unroll
    for (int r = 0; r < 3; r++) {
        int u = tu + 16 * r;
        if (u < Uq) {
#pragma unroll
            for (int j = 0; j < 4; j++)
                g_part[((bh * NKC + kc) * Uq + u) * Dq + td + 16 * j] = acc[r][j];
        }
    }
}

// ---------------- Stage 4: V mean (partials, then fixed-order combine) ----------------
__global__ void __launch_bounds__(256) kernel_meanpart(const float* __restrict__ V) {
    int lc = blockIdx.x;   // 0..15, 256 l's each
    int bh = blockIdx.y;
    int b = bh >> 3, h = bh & 7;
    int tid = threadIdx.x;
    int d = tid & 63, c = tid >> 6;  // c: 0..3, 64 l's each
    __shared__ float red[256];
    float s = 0.f;
    int lb = lc * 256 + c * 64;
    for (int i = 0; i < 64; i++)
        s += V[(((size_t)b * Lq + lb + i) * Hq + h) * Dq + d];
    red[tid] = s;
    __syncthreads();
    if (c == 0)
        g_meanp[(bh * 16 + lc) * Dq + d] = red[d] + red[64 + d] + red[128 + d] + red[192 + d];
}

__global__ void __launch_bounds__(256) kernel_meancomb() {
    int e = blockIdx.x * 256 + threadIdx.x;
    if (e >= BHq * Dq) return;
    int bh = e >> 6, d = e & 63;
    float s = 0.f;
#pragma unroll
    for (int lc = 0; lc < 16; lc++) s += g_meanp[(bh * 16 + lc) * Dq + d];
    g_meanv[bh * Dq + d] = s * (1.f / Lq);
}

// ---------------- Stage 5: broadcast fill of context with V mean (float4 stores) ----------------
__global__ void __launch_bounds__(256) kernel_fill(float4* __restrict__ out) {
    int i = blockIdx.x * 256 + threadIdx.x;      // 2097152 float4's
    int bh = i >> 16;
    int d4 = i & 15;
    out[i] = ((const float4*)g_meanv)[bh * 16 + d4];
}

// ---------------- Stage 6: reduce split-K partials, normalize, scatter into output ----------------
__global__ void __launch_bounds__(256) kernel_final(float* __restrict__ out) {
    int e = blockIdx.x * 256 + threadIdx.x;
    if (e >= BHq * Uq * Dq) return;
    int d = e & 63;
    int t = e >> 6;
    int u = t % Uq;
    int bh = t / Uq;
    float s = 0.f;
#pragma unroll
    for (int c = 0; c < NKC; c++) s += g_part[((bh * NKC + c) * Uq + u) * Dq + d];
    s /= g_rowsum[bh * Uq + u];
    int row = g_top[bh * Uq + u];
    out[((size_t)bh * Lq + row) * Dq + d] = s;
}

// ---------------- launch ----------------
extern "C" void kernel_launch(void* const* d_in, const int* in_sizes, int n_in,
                              void* d_out, int out_size) {
    const float* Q   = (const float*)d_in[0];
    const float* K   = (const float*)d_in[1];
    const float* V   = (const float*)d_in[2];
    const int*   idx = (const int*)d_in[3];
    float* out = (float*)d_out;

    kernel_m       <<<BHq * (Lq / 4), 128>>>(Q, K, idx);
    kernel_topk    <<<BHq, 256>>>();
    kernel_scores  <<<dim3(Lq / 128, BHq), 256>>>(Q, K);
    kernel_comb    <<<(BHq * Uq + 7) / 8, 256>>>();
    kernel_updpart <<<dim3(NKC, BHq), 256>>>(V);
    kernel_meanpart<<<dim3(16, BHq), 256>>>(V);
    kernel_meancomb<<<(BHq * Dq + 255) / 256, 256>>>();
    kernel_fill    <<<(BHq * Lq * Dq / 4) / 256, 256>>>((float4*)out);
    kernel_final   <<<(BHq * Uq * Dq + 255) / 256, 256>>>(out);
}

// round 8
// speedup vs baseline: 1.4377x; 1.1265x over previous
#include <cuda_runtime.h>
#include <math_constants.h>

// Problem constants (fixed instance: B=4, L=4096, H=8, D=64, sample_k=n_top=45)
#define Bq  4
#define Lq  4096
#define Hq  8
#define Dq  64
#define Sq  45      // sample_k
#define Uq  45      // n_top
#define BHq 32
#define NKC 8       // key chunks for split-K attn*V
#define KCS 512     // keys per chunk
#define NKB 32      // 128-key blocks per row (Lq/128) for partial softmax stats

// ---------------- scratch (device globals: alloc-free) ----------------
__device__ float g_M[BHq * Lq];                 // 512 KB
__device__ int   g_top[BHq * Uq];
__device__ float g_scores[BHq * Uq * Lq];       // 23.6 MB
__device__ float g_pmax[BHq * Uq * NKB];        // per-key-block max
__device__ float g_psum[BHq * Uq * NKB];        // per-key-block sum(exp(.-blockmax))
__device__ float g_rowmax[BHq * Uq];
__device__ float g_rowsum[BHq * Uq];
__device__ float g_part[BHq * NKC * Uq * Dq];   // split-K partials
__device__ float g_meanp[BHq * 16 * Dq];        // V-mean partials
__device__ float g_meanv[BHq * Dq];

// ---- cp.async helpers (16B, keep L1) ----
__device__ __forceinline__ void cp_async16(void* smem_dst, const void* gsrc) {
    unsigned s = (unsigned)__cvta_generic_to_shared(smem_dst);
    asm volatile("cp.async.ca.shared.global [%0], [%1], 16;\n" :: "r"(s), "l"(gsrc));
}
__device__ __forceinline__ void cp_async_wait_all() {
    asm volatile("cp.async.commit_group;\n");
    asm volatile("cp.async.wait_group 0;\n");
}

// ---------------- Stage 1: M[b,h,l] = max_s(q.k_s) - sum_s(q.k_s)/L ----------------
// CTA = 128 threads = 4 queries. Phase 0: stage the CTA's 180 idx values into
// smem (contiguous slab, coalesced). Phase 1: gather the 180 K rows via
// cp.async (LDGSTS: no register staging, all ~23 copies per thread in flight
// -> L2-BW-bound instead of latency-bound). Phase 2: lane-per-sample dots from
// padded smem (17-float4 stride: LDS.128 phases cover all 32 banks).
__global__ void __launch_bounds__(128) kernel_m(const float* __restrict__ Q,
                                                const float* __restrict__ K,
                                                const int*   __restrict__ idx) {
    __shared__ int    sidx[4 * Sq];
    __shared__ float4 ks[4 * Sq * 17];           // 48,960 B
    int tid = threadIdx.x;
    int bh = blockIdx.x >> 10;                   // 1024 CTAs per (b,h)
    int l0 = (blockIdx.x & 1023) * 4;
    int b = bh >> 3, h = bh & 7;

    int w    = tid >> 5;
    int lane = tid & 31;
    int l = l0 + w;

    // idx slab for queries l0..l0+3 is contiguous: idx[l0*45 .. l0*45+180)
    for (int e = tid; e < 4 * Sq; e += 128) sidx[e] = idx[l0 * Sq + e];

    // q row into registers (uniform per warp -> broadcast loads)
    const float4* qrow = (const float4*)(Q + (((size_t)b * Lq + l) * Hq + h) * Dq);
    float4 q[16];
#pragma unroll
    for (int i = 0; i < 16; i++) q[i] = qrow[i];

    __syncthreads();

    // fire-and-forget gather of 180 K rows (16B per cp.async)
    const float* Kbh = K + ((size_t)b * Lq * Hq + h) * Dq;
#pragma unroll 4
    for (int e = tid; e < 4 * Sq * 16; e += 128) {
        int row = e >> 4, seg = e & 15;
        int j = sidx[row];
        cp_async16(&ks[row * 17 + seg],
                   (const float4*)(Kbh + (size_t)j * (Hq * Dq)) + seg);
    }
    cp_async_wait_all();
    __syncthreads();

    float lm = -CUDART_INF_F;
    float ls = 0.f;
#pragma unroll
    for (int r = 0; r < 2; r++) {
        int s = lane + 32 * r;
        if (s < Sq) {
            const float4* kr = &ks[(w * Sq + s) * 17];
            float dot = 0.f;
#pragma unroll
            for (int i = 0; i < 16; i++) {
                float4 kv = kr[i];
                dot = fmaf(q[i].x, kv.x, dot);
                dot = fmaf(q[i].y, kv.y, dot);
                dot = fmaf(q[i].z, kv.z, dot);
                dot = fmaf(q[i].w, kv.w, dot);
            }
            lm = fmaxf(lm, dot);
            ls += dot;
        }
    }
#pragma unroll
    for (int o = 16; o > 0; o >>= 1) {
        lm = fmaxf(lm, __shfl_xor_sync(0xffffffffu, lm, o));
        ls += __shfl_xor_sync(0xffffffffu, ls, o);
    }
    if (lane == 0) g_M[bh * Lq + l] = lm - ls * (1.f / Lq);
}

// ---------------- Stage 2: top-45 per (b,h), stable (lowest index on ties) ----------------
__global__ void __launch_bounds__(256) kernel_topk() {
    int bh = blockIdx.x;
    __shared__ float v[Lq];
    __shared__ float bv[256];
    __shared__ int   bi[256];
    int t = threadIdx.x;
    for (int i = t; i < Lq; i += 256) v[i] = g_M[bh * Lq + i];
    __syncthreads();
    for (int u = 0; u < Uq; u++) {
        float best = -CUDART_INF_F;
        int   besti = Lq;
        for (int i = t; i < Lq; i += 256) {
            float x = v[i];
            if (x > best) { best = x; besti = i; }   // strided ascending -> lowest idx kept on tie
        }
        bv[t] = best; bi[t] = besti;
        __syncthreads();
        for (int st = 128; st > 0; st >>= 1) {
            if (t < st) {
                if (bv[t + st] > bv[t] || (bv[t + st] == bv[t] && bi[t + st] < bi[t])) {
                    bv[t] = bv[t + st]; bi[t] = bi[t + st];
                }
            }
            __syncthreads();
        }
        if (t == 0) { g_top[bh * Uq + u] = bi[0]; v[bi[0]] = -CUDART_INF_F; }
        __syncthreads();
    }
}

// ---------------- Stage 3a: scores + fused per-block softmax stats ----------------
__global__ void __launch_bounds__(256) kernel_scores(const float* __restrict__ Q,
                                                     const float* __restrict__ K) {
    __shared__ float Qs[Uq * 65];
    __shared__ float Ks[128 * 65];
    int bh = blockIdx.y;
    int kb = blockIdx.x;
    int b = bh >> 3, h = bh & 7;
    int tid = threadIdx.x;

    for (int e = tid; e < Uq * Dq; e += 256) {
        int u = e >> 6, d = e & 63;
        int row = g_top[bh * Uq + u];
        Qs[u * 65 + d] = Q[(((size_t)b * Lq + row) * Hq + h) * Dq + d];
    }
    int k0 = kb * 128;
    for (int e = tid; e < 128 * Dq; e += 256) {
        int k = e >> 6, d = e & 63;
        Ks[k * 65 + d] = K[(((size_t)b * Lq + k0 + k) * Hq + h) * Dq + d];
    }
    __syncthreads();

    int tu = tid >> 4, tk = tid & 15;
    float acc[3][8];
#pragma unroll
    for (int r = 0; r < 3; r++)
#pragma unroll
        for (int j = 0; j < 8; j++) acc[r][j] = 0.f;

#pragma unroll 4
    for (int d = 0; d < Dq; d++) {
        float qv[3];
#pragma unroll
        for (int r = 0; r < 3; r++) {
            int u = tu + 16 * r;
            qv[r] = (u < Uq) ? Qs[u * 65 + d] : 0.f;
        }
        float kv[8];
#pragma unroll
        for (int j = 0; j < 8; j++) kv[j] = Ks[(tk + 16 * j) * 65 + d];
#pragma unroll
        for (int r = 0; r < 3; r++)
#pragma unroll
            for (int j = 0; j < 8; j++) acc[r][j] = fmaf(qv[r], kv[j], acc[r][j]);
    }

#pragma unroll
    for (int r = 0; r < 3; r++) {
        int u = tu + 16 * r;
        float sc[8];
#pragma unroll
        for (int j = 0; j < 8; j++) sc[j] = acc[r][j] * 0.125f;
        if (u < Uq) {
#pragma unroll
            for (int j = 0; j < 8; j++)
                g_scores[(bh * Uq + u) * Lq + k0 + tk + 16 * j] = sc[j];
        }
        float m = sc[0];
#pragma unroll
        for (int j = 1; j < 8; j++) m = fmaxf(m, sc[j]);
#pragma unroll
        for (int o = 8; o > 0; o >>= 1) m = fmaxf(m, __shfl_xor_sync(0xffffffffu, m, o));
        float s = 0.f;
#pragma unroll
        for (int j = 0; j < 8; j++) s += expf(sc[j] - m);
#pragma unroll
        for (int o = 8; o > 0; o >>= 1) s += __shfl_xor_sync(0xffffffffu, s, o);
        if (tk == 0 && u < Uq) {
            g_pmax[(bh * Uq + u) * NKB + kb] = m;
            g_psum[(bh * Uq + u) * NKB + kb] = s;
        }
    }
}

// ---------------- Stage 3b: combine 32 block partials -> row max / row sum ----------------
__global__ void __launch_bounds__(256) kernel_comb() {
    int gw = blockIdx.x * 8 + (threadIdx.x >> 5);   // one warp per (bh,u) row
    if (gw >= BHq * Uq) return;
    int lane = threadIdx.x & 31;
    float pm = g_pmax[gw * NKB + lane];
    float ps = g_psum[gw * NKB + lane];
    float rm = pm;
#pragma unroll
    for (int o = 16; o > 0; o >>= 1) rm = fmaxf(rm, __shfl_xor_sync(0xffffffffu, rm, o));
    float c = ps * expf(pm - rm);
#pragma unroll
    for (int o = 16; o > 0; o >>= 1) c += __shfl_xor_sync(0xffffffffu, c, o);
    if (lane == 0) { g_rowmax[gw] = rm; g_rowsum[gw] = c; }
}

// ---------------- Stage 3c: split-K partial upd[u][d] = sum_k w[u,k] * V[k,d] ----------------
__global__ void __launch_bounds__(256) kernel_updpart(const float* __restrict__ V) {
    __shared__ float Vs[64 * 65];
    __shared__ float Ws[Uq * 65];
    int bh = blockIdx.y;
    int kc = blockIdx.x;   // 0..7
    int b = bh >> 3, h = bh & 7;
    int tid = threadIdx.x;
    int tu = tid >> 4, td = tid & 15;

    float acc[3][4];
#pragma unroll
    for (int r = 0; r < 3; r++)
#pragma unroll
        for (int j = 0; j < 4; j++) acc[r][j] = 0.f;

    for (int sub = 0; sub < 8; sub++) {
        int kbase = kc * KCS + sub * 64;
        for (int e = tid; e < 64 * 64; e += 256) {
            int k = e >> 6, d = e & 63;
            Vs[k * 65 + d] = V[(((size_t)b * Lq + kbase + k) * Hq + h) * Dq + d];
        }
        for (int e = tid; e < Uq * 64; e += 256) {
            int u = e >> 6, k = e & 63;
            Ws[u * 65 + k] = expf(g_scores[(bh * Uq + u) * Lq + kbase + k] - g_rowmax[bh * Uq + u]);
        }
        __syncthreads();
#pragma unroll 4
        for (int k = 0; k < 64; k++) {
            float wv[3];
#pragma unroll
            for (int r = 0; r < 3; r++) {
                int u = tu + 16 * r;
                wv[r] = (u < Uq) ? Ws[u * 65 + k] : 0.f;
            }
            float vv[4];
#pragma unroll
            for (int j = 0; j < 4; j++) vv[j] = Vs[k * 65 + td + 16 * j];
#pragma unroll
            for (int r = 0; r < 3; r++)
#pragma unroll
                for (int j = 0; j < 4; j++) acc[r][j] = fmaf(wv[r], vv[j], acc[r][j]);
        }
        __syncthreads();
    }
#pragma unroll
    for (int r = 0; r < 3; r++) {
        int u = tu + 16 * r;
        if (u < Uq) {
#pragma unroll
            for (int j = 0; j < 4; j++)
                g_part[((bh * NKC + kc) * Uq + u) * Dq + td + 16 * j] = acc[r][j];
        }
    }
}

// ---------------- Stage 4: V mean (partials, then fixed-order combine) ----------------
__global__ void __launch_bounds__(256) kernel_meanpart(const float* __restrict__ V) {
    int lc = blockIdx.x;   // 0..15, 256 l's each
    int bh = blockIdx.y;
    int b = bh >> 3, h = bh & 7;
    int tid = threadIdx.x;
    int d = tid & 63, c = tid >> 6;  // c: 0..3, 64 l's each
    __shared__ float red[256];
    float s = 0.f;
    int lb = lc * 256 + c * 64;
    for (int i = 0; i < 64; i++)
        s += V[(((size_t)b * Lq + lb + i) * Hq + h) * Dq + d];
    red[tid] = s;
    __syncthreads();
    if (c == 0)
        g_meanp[(bh * 16 + lc) * Dq + d] = red[d] + red[64 + d] + red[128 + d] + red[192 + d];
}

__global__ void __launch_bounds__(256) kernel_meancomb() {
    int e = blockIdx.x * 256 + threadIdx.x;
    if (e >= BHq * Dq) return;
    int bh = e >> 6, d = e & 63;
    float s = 0.f;
#pragma unroll
    for (int lc = 0; lc < 16; lc++) s += g_meanp[(bh * 16 + lc) * Dq + d];
    g_meanv[bh * Dq + d] = s * (1.f / Lq);
}

// ---------------- Stage 5: broadcast fill of context with V mean (float4 stores) ----------------
__global__ void __launch_bounds__(256) kernel_fill(float4* __restrict__ out) {
    int i = blockIdx.x * 256 + threadIdx.x;      // 2097152 float4's
    int bh = i >> 16;
    int d4 = i & 15;
    out[i] = ((const float4*)g_meanv)[bh * 16 + d4];
}

// ---------------- Stage 6: reduce split-K partials, normalize, scatter into output ----------------
__global__ void __launch_bounds__(256) kernel_final(float* __restrict__ out) {
    int e = blockIdx.x * 256 + threadIdx.x;
    if (e >= BHq * Uq * Dq) return;
    int d = e & 63;
    int t = e >> 6;
    int u = t % Uq;
    int bh = t / Uq;
    float s = 0.f;
#pragma unroll
    for (int c = 0; c < NKC; c++) s += g_part[((bh * NKC + c) * Uq + u) * Dq + d];
    s /= g_rowsum[bh * Uq + u];
    int row = g_top[bh * Uq + u];
    out[((size_t)bh * Lq + row) * Dq + d] = s;
}

// ---------------- launch ----------------
extern "C" void kernel_launch(void* const* d_in, const int* in_sizes, int n_in,
                              void* d_out, int out_size) {
    const float* Q   = (const float*)d_in[0];
    const float* K   = (const float*)d_in[1];
    const float* V   = (const float*)d_in[2];
    const int*   idx = (const int*)d_in[3];
    float* out = (float*)d_out;

    kernel_m       <<<BHq * (Lq / 4), 128>>>(Q, K, idx);
    kernel_topk    <<<BHq, 256>>>();
    kernel_scores  <<<dim3(Lq / 128, BHq), 256>>>(Q, K);
    kernel_comb    <<<(BHq * Uq + 7) / 8, 256>>>();
    kernel_updpart <<<dim3(NKC, BHq), 256>>>(V);
    kernel_meanpart<<<dim3(16, BHq), 256>>>(V);
    kernel_meancomb<<<(BHq * Dq + 255) / 256, 256>>>();
    kernel_fill    <<<(BHq * Lq * Dq / 4) / 256, 256>>>((float4*)out);
    kernel_final   <<<(BHq * Uq * Dq + 255) / 256, 256>>>(out);
}